// round 16
// baseline (speedup 1.0000x reference)
#include <cuda_runtime.h>
#include <cuda_fp16.h>
#include <math.h>
#include <cstdint>

// ---------------------------------------------------------------------------
// Problem constants (fixed by setup_inputs)
// ---------------------------------------------------------------------------
namespace {
constexpr int kBN   = 16;
constexpr int kT    = 12;
constexpr int kCH   = 128;
constexpr int kH    = 24, kW = 24;
constexpr int kHW   = 576;
constexpr int kTm1  = 11;
constexpr int kTp   = 9;
constexpr int kNB   = 144;    // kBN * kTp
constexpr int kSSTA = 32;
constexpr int kCP   = 114;
constexpr int kOutC = 456;    // 4 * kCP
constexpr int kNAtt = 176;    // kBN * kTm1
constexpr float kScale = 0.0883883476483184f;  // 128^-0.5
}

// ---------------------------------------------------------------------------
// Low-level helpers
// ---------------------------------------------------------------------------
__device__ __forceinline__ unsigned long long pack2(float lo, float hi) {
    unsigned long long r;
    asm("mov.b64 %0, {%1, %2};" : "=l"(r) : "f"(lo), "f"(hi));
    return r;
}
__device__ __forceinline__ unsigned long long dup2(float v) { return pack2(v, v); }
__device__ __forceinline__ void ffma2(unsigned long long& d, unsigned long long a,
                                      unsigned long long b) {
    asm("fma.rn.f32x2 %0, %1, %2, %3;" : "=l"(d) : "l"(a), "l"(b), "l"(d));
}
__device__ __forceinline__ void unpack2(unsigned long long v, float& lo, float& hi) {
    asm("mov.b64 {%0, %1}, %2;" : "=f"(lo), "=f"(hi) : "l"(v));
}

// fp16 MMA m16n8k16 (legacy HMMA path -- valid on non-'a' sm_103 target)
__device__ __forceinline__ void mma16816(float* c, const uint32_t* a, const uint32_t* b) {
    asm volatile(
        "mma.sync.aligned.m16n8k16.row.col.f32.f16.f16.f32 "
        "{%0,%1,%2,%3}, {%4,%5,%6,%7}, {%8,%9}, {%0,%1,%2,%3};"
        : "+f"(c[0]), "+f"(c[1]), "+f"(c[2]), "+f"(c[3])
        : "r"(a[0]), "r"(a[1]), "r"(a[2]), "r"(a[3]), "r"(b[0]), "r"(b[1]));
}

__device__ __forceinline__ uint32_t smem_u32p(const void* p) {
    uint32_t a;
    asm("{ .reg .u64 t; cvta.to.shared.u64 t, %1; cvt.u32.u64 %0, t; }"
        : "=r"(a) : "l"(p));
    return a;
}
__device__ __forceinline__ void ldm_x4(uint32_t* r, uint32_t saddr) {
    asm volatile("ldmatrix.sync.aligned.m8n8.x4.shared.b16 {%0,%1,%2,%3}, [%4];"
                 : "=r"(r[0]), "=r"(r[1]), "=r"(r[2]), "=r"(r[3]) : "r"(saddr));
}
__device__ __forceinline__ void cpasync16(void* sdst, const void* gsrc) {
    asm volatile("cp.async.ca.shared.global [%0], [%1], 16;"
                 :: "r"(smem_u32p(sdst)), "l"(gsrc));
}
__device__ __forceinline__ void cp_commit() {
    asm volatile("cp.async.commit_group;" ::: "memory");
}
__device__ __forceinline__ void cp_wait1() {
    asm volatile("cp.async.wait_group 1;" ::: "memory");
}
__device__ __forceinline__ void cp_wait0() {
    asm volatile("cp.async.wait_group 0;" ::: "memory");
}

// pack two fp16 from floats
__device__ __forceinline__ uint32_t h2pack(float x, float y) {
    __half hx = __float2half_rn(x), hy = __float2half_rn(y);
    return ((uint32_t)__half_as_ushort(hy) << 16) | __half_as_ushort(hx);
}

// ---------------------------------------------------------------------------
// Scratch (static device globals)
// ---------------------------------------------------------------------------
__device__ __half g_xT[((size_t)kBN * kT * kHW + 64) * kCH];
// fp16 logits written by energy; softmax converts IN PLACE to attn probs.
__device__ __half g_attn_h[((size_t)kNAtt * kHW + 64) * kHW];
__device__ __half g_acc0[((size_t)kNB * kCP + 128) * kHW];
__device__ __half g_acc1[((size_t)kNB * 2 * kCP + 128) * kHW];
__device__ __half g_acc2[((size_t)kNB * 3 * kCP + 128) * kHW];

__device__ __forceinline__ __half* acc_buf(int s) {
    return s == 0 ? g_acc0 : (s == 1 ? g_acc1 : g_acc2);
}

// ---------------------------------------------------------------------------
// Templated SMEM tile buffer + GEMM core.  128(m) x 128(n) CTA tile.
// KT = K-elements per tile, LDS = row stride in halves (KT + 8, conflict-free:
// 72 halves = 144B, 104 halves = 208B; both give 8 distinct ldmatrix phases).
// ---------------------------------------------------------------------------
template <int KT, int LDS>
struct BufT {
    __half Ah[128 * LDS];
    __half Bh[128 * LDS];
};

template <int KT, int LDS>
__device__ __forceinline__ void stage_tile(
    BufT<KT, LDS>& d, const __half* __restrict__ Agh, int lda,
    const __half* __restrict__ Bgh, int ldb, int k0, int tid) {
    constexpr int CPR = KT / 8;           // 16B chunks per row
    constexpr int CPM = 128 * CPR;        // chunks per matrix
#pragma unroll
    for (int s = 0; s < 2 * CPM / 256; s++) {
        int i = s * 256 + tid;
        if (i < CPM) {
            int row = i / CPR, c = i % CPR;
            cpasync16(&d.Ah[row * LDS + c * 8], Agh + (size_t)row * lda + k0 + c * 8);
        } else {
            int ii = i - CPM;
            int row = ii / CPR, c = ii % CPR;
            cpasync16(&d.Bh[row * LDS + c * 8], Bgh + (size_t)row * ldb + k0 + c * 8);
        }
    }
}

template <int LDS>
__device__ __forceinline__ void load_bfrags(uint32_t bf[8][2], uint32_t Bh0, uint32_t kbb) {
#pragma unroll
    for (int half = 0; half < 2; half++) {
        uint32_t roff = (uint32_t)(half * 32 * LDS * 2) + kbb;
        uint32_t t[4];
        ldm_x4(t, Bh0 + roff);
        bf[half * 4 + 0][0] = t[0]; bf[half * 4 + 0][1] = t[1];
        bf[half * 4 + 1][0] = t[2]; bf[half * 4 + 1][1] = t[3];
        ldm_x4(t, Bh0 + roff + 16 * LDS * 2);
        bf[half * 4 + 2][0] = t[0]; bf[half * 4 + 2][1] = t[1];
        bf[half * 4 + 3][0] = t[2]; bf[half * 4 + 3][1] = t[3];
    }
}

// Core: C[128x128] over K (multiple of KT). 8 warps = 4(m) x 2(n), warp tile
// 32(m) x 64(n). ldmatrix fragments; B frags software-pipelined.
template <int KT, int LDS>
__device__ __forceinline__ void gemm_core(
    const __half* __restrict__ Agh, int lda,
    const __half* __restrict__ Bgh, int ldb,
    int K, float acc[2][8][4], BufT<KT, LDS>* bufs) {
    int tid = threadIdx.x;
    int wid = tid >> 5, lane = tid & 31;
    int wm = wid & 3, wn = wid >> 2;

    int j = lane >> 3, r = lane & 7;
    uint32_t aoff = (uint32_t)(((wm * 32 + ((j & 1) << 3) + r) * LDS + ((j >> 1) << 3)) * 2);
    uint32_t boff = (uint32_t)(((wn * 64 + ((j >> 1) << 3) + r) * LDS + ((j & 1) << 3)) * 2);

#pragma unroll
    for (int i = 0; i < 2; i++)
#pragma unroll
        for (int jj = 0; jj < 8; jj++)
#pragma unroll
            for (int q = 0; q < 4; q++) acc[i][jj][q] = 0.f;

    int nt = K / KT;
    stage_tile<KT, LDS>(bufs[0], Agh, lda, Bgh, ldb, 0, tid);
    cp_commit();
    for (int kt = 0; kt < nt; kt++) {
        if (kt + 1 < nt) {
            stage_tile<KT, LDS>(bufs[(kt + 1) & 1], Agh, lda, Bgh, ldb, (kt + 1) * KT, tid);
            cp_commit();
            cp_wait1();
        } else {
            cp_wait0();
        }
        __syncthreads();
        BufT<KT, LDS>& b = bufs[kt & 1];
        uint32_t Ah0 = smem_u32p(b.Ah) + aoff;
        uint32_t Bh0 = smem_u32p(b.Bh) + boff;

        uint32_t bbuf[2][8][2];
        load_bfrags<LDS>(bbuf[0], Bh0, 0);
#pragma unroll
        for (int kb = 0; kb < KT / 16; kb++) {
            int cur = kb & 1;
            uint32_t kbb = (uint32_t)kb * 32;  // 16 halves = 32 bytes per k-step
            uint32_t ah[2][4];
            ldm_x4(ah[0], Ah0 + kbb);
            ldm_x4(ah[1], Ah0 + 16 * LDS * 2 + kbb);
            if (kb < KT / 16 - 1) load_bfrags<LDS>(bbuf[cur ^ 1], Bh0, kbb + 32);
#pragma unroll
            for (int jj = 0; jj < 8; jj++)
#pragma unroll
                for (int mi = 0; mi < 2; mi++)
                    mma16816(acc[mi][jj], ah[mi], bbuf[cur][jj]);
        }
        __syncthreads();
    }
}

using BufE = BufT<64, 72>;    // energy: K=128, 2 tiles;  2*36864  = 73728 B
using BufP = BufT<96, 104>;   // prop:   K=576, 6 tiles;  2*53248  = 106496 B
constexpr int kSmemE = 2 * sizeof(BufE);
constexpr int kSmemP = 2 * sizeof(BufP);

// ---------------------------------------------------------------------------
// 1) Normalize + transpose + fp16 convert: g_xT[bt*HW+pix][c]
// ---------------------------------------------------------------------------
__global__ __launch_bounds__(256) void normalize_t_kernel(const float* __restrict__ x) {
    __shared__ float sm[128][65];
    __shared__ float psum[4][64];
    __shared__ float invs[64];
    int bt = blockIdx.x, p0 = blockIdx.y * 64;
    int tid = threadIdx.x;
    int px = tid & 63, cq = tid >> 6;
    const float* xb = x + (size_t)bt * kCH * kHW + p0;
    float s = 0.f;
#pragma unroll
    for (int j = 0; j < 32; j++) {
        int c = cq * 32 + j;
        float v = xb[(size_t)c * kHW + px];
        sm[c][px] = v;
        s += v * v;
    }
    psum[cq][px] = s;
    __syncthreads();
    if (tid < 64) {
        float tot = psum[0][tid] + psum[1][tid] + psum[2][tid] + psum[3][tid];
        invs[tid] = 1.0f / fmaxf(sqrtf(tot), 1e-12f);
    }
    __syncthreads();
    float iv = invs[px];
    size_t rb = ((size_t)bt * kHW + p0 + px) * kCH + cq * 32;
#pragma unroll
    for (int j4 = 0; j4 < 8; j4++) {
        int c = cq * 32 + j4 * 4;
        uint32_t w0 = h2pack(sm[c][px] * iv, sm[c + 1][px] * iv);
        uint32_t w1 = h2pack(sm[c + 2][px] * iv, sm[c + 3][px] * iv);
        *(uint2*)(g_xT + rb + j4 * 4) = make_uint2(w0, w1);
    }
}

// ---------------------------------------------------------------------------
// 2) Value projection FUSED with cs-scatter (channels 32..127 only).
// ---------------------------------------------------------------------------
__global__ __launch_bounds__(256) void vproj_fused_kernel(const float* __restrict__ x,
                                                          const float* __restrict__ Wv,
                                                          const float* __restrict__ bv,
                                                          float* __restrict__ outp) {
    int bt = blockIdx.y;
    int p0 = blockIdx.x * 64;
    int b = bt / kT, tt = bt % kT;
    __shared__ __align__(16) float Ws[16][100];  // [c][o'] o'=0..95
    __shared__ __align__(16) float Xs[16][68];
    int tid = threadIdx.x;
    int ty = tid >> 4, tx = tid & 15;
    unsigned long long acc[3][4];
#pragma unroll
    for (int i = 0; i < 3; i++)
#pragma unroll
        for (int j = 0; j < 4; j++) acc[i][j] = 0ULL;

    const float* xb = x + (size_t)bt * kCH * kHW;
    for (int c0 = 0; c0 < kCH; c0 += 16) {
#pragma unroll
        for (int r = 0; r < 6; r++) {            // 96 o x 16 c
            int lin = r * 256 + tid;
            int o = lin >> 4, c = lin & 15;
            Ws[c][o] = Wv[(kSSTA + o) * kCH + c0 + c];
        }
#pragma unroll
        for (int r = 0; r < 4; r++) {
            int lin = r * 256 + tid;
            int c = lin >> 6, j = lin & 63;
            Xs[c][j] = xb[(size_t)(c0 + c) * kHW + p0 + j];
        }
        __syncthreads();
#pragma unroll
        for (int c = 0; c < 16; c++) {
            float4 xv = *(const float4*)&Xs[c][tx * 4];
            float w0 = Ws[c][ty * 6 + 0], w1 = Ws[c][ty * 6 + 1];
            float w2 = Ws[c][ty * 6 + 2], w3 = Ws[c][ty * 6 + 3];
            float w4 = Ws[c][ty * 6 + 4], w5 = Ws[c][ty * 6 + 5];
            unsigned long long wp[3] = {pack2(w0, w1), pack2(w2, w3), pack2(w4, w5)};
            unsigned long long xd[4] = {dup2(xv.x), dup2(xv.y), dup2(xv.z), dup2(xv.w)};
#pragma unroll
            for (int i = 0; i < 3; i++)
#pragma unroll
                for (int j = 0; j < 4; j++) ffma2(acc[i][j], wp[i], xd[j]);
        }
        __syncthreads();
    }

#pragma unroll
    for (int i = 0; i < 3; i++) {
        int cd0 = ty * 6 + 2 * i;
        float b0 = bv[kSSTA + cd0], b1 = bv[kSSTA + cd0 + 1];
        float vlo[4], vhi[4];
#pragma unroll
        for (int j = 0; j < 4; j++) {
            float lo, hi;
            unpack2(acc[i][j], lo, hi);
            vlo[j] = lo + b0;
            vhi[j] = hi + b1;
        }
        int pix = p0 + tx * 4;
        uint2 hlo = make_uint2(h2pack(vlo[0], vlo[1]), h2pack(vlo[2], vlo[3]));
        uint2 hhi = make_uint2(h2pack(vhi[0], vhi[1]), h2pack(vhi[2], vhi[3]));
#pragma unroll
        for (int s = 0; s < 4; s++) {
            int t = tt - s;
            if (t >= 0 && t < kTp) {
                int bz = b * kTp + t;
                if (s == 3) {
                    float* d = outp + ((size_t)bz * kOutC + cd0) * kHW + pix;
                    *(float4*)d = make_float4(vlo[0], vlo[1], vlo[2], vlo[3]);
                    *(float4*)(d + kHW) = make_float4(vhi[0], vhi[1], vhi[2], vhi[3]);
                } else {
                    int dc = (s + 1) * kCP;
                    __half* d = acc_buf(s) + ((size_t)bz * dc + cd0) * kHW + pix;
                    *(uint2*)d = hlo;
                    *(uint2*)(d + kHW) = hhi;
                }
            }
        }
    }
}

// ---------------------------------------------------------------------------
// 3) Positional-encoding FUSED scatter: cs channels 96..113 for all stages.
// ---------------------------------------------------------------------------
__global__ __launch_bounds__(256) void pe_fill_fused_kernel(float* __restrict__ outp) {
    int gid = blockIdx.x * 256 + threadIdx.x;
    const int total = kBN * kT * 18 * kHW;
    if (gid >= total) return;
    int bt  = gid / (18 * kHW);
    int rem = gid % (18 * kHW);
    int c = rem / kHW, pix = rem % kHW;
    int yy = pix / kW, xx = pix % kW;
    float yc = -1.0f + 2.0f * (float)yy / (float)(kH - 1);
    float xc = -1.0f + 2.0f * (float)xx / (float)(kW - 1);
    float val;
    if (c == 0) val = yc;
    else if (c == 1) val = xc;
    else {
        int i = (c - 2) >> 2;
        int k = (c - 2) & 3;
        float coord = (k & 1) ? xc : yc;
        float f = (float)(1 << i) * 3.14159265358979323846f * coord;
        val = (k < 2) ? sinf(f) : cosf(f);
    }
    int b = bt / kT, tt = bt % kT;
    int cd = 96 + c;
    __half hv = __float2half_rn(val);
#pragma unroll
    for (int s = 0; s < 4; s++) {
        int t = tt - s;
        if (t >= 0 && t < kTp) {
            int bz = b * kTp + t;
            if (s == 3)
                outp[((size_t)bz * kOutC + cd) * kHW + pix] = val;
            else
                acc_buf(s)[((size_t)bz * (s + 1) * kCP + cd) * kHW + pix] = hv;
        }
    }
}

// ---------------------------------------------------------------------------
// 4) Energy GEMM: logits[g,n,m] = scale * sum_c qT[n,c]*kT[m,c]; out fp16.
//    grid = (5 m-tiles(128), 5 n-tiles(128), 176 g)
// ---------------------------------------------------------------------------
__global__ __launch_bounds__(256, 2) void energy_mma_kernel() {
    extern __shared__ __align__(16) char smem[];
    int g = blockIdx.z;
    int b = g / kTm1, t = g % kTm1;
    int m0 = blockIdx.y * 128, n0 = blockIdx.x * 128;
    size_t abase = ((size_t)(b * kT + t + 1) * kHW + m0) * kCH;
    size_t bbase = ((size_t)(b * kT + t) * kHW + n0) * kCH;
    float acc[2][8][4];
    gemm_core<64, 72>(g_xT + abase, kCH, g_xT + bbase, kCH, kCH, acc, (BufE*)smem);

    int tid = threadIdx.x;
    int wid = tid >> 5, lane = tid & 31;
    int quad = lane >> 2, tq = lane & 3;
    int wm = wid & 3, wn = wid >> 2;
    int mvalid = kHW - m0;
    __half* C = g_attn_h + (size_t)g * kHW * kHW + (size_t)m0 * kHW;
#pragma unroll
    for (int mi = 0; mi < 2; mi++)
#pragma unroll
        for (int rh = 0; rh < 2; rh++) {
            int rrow = wm * 32 + mi * 16 + quad + rh * 8;
            if (rrow < mvalid) {
#pragma unroll
                for (int ni = 0; ni < 8; ni++) {
                    int ncol = n0 + wn * 64 + ni * 8 + tq * 2;
                    if (ncol < kHW) {
                        uint32_t hw = h2pack(acc[mi][ni][rh * 2] * kScale,
                                             acc[mi][ni][rh * 2 + 1] * kScale);
                        *(uint32_t*)(C + (size_t)rrow * kHW + ncol) = hw;
                    }
                }
            }
        }
}

// ---------------------------------------------------------------------------
// 5) Softmax: one warp per row, 8 rows per block, IN PLACE fp16.
// ---------------------------------------------------------------------------
__global__ __launch_bounds__(256) void softmax_kernel() {
    int wid = threadIdx.x >> 5, lane = threadIdx.x & 31;
    size_t row = (size_t)blockIdx.x * 8 + wid;
    __half2* p = (__half2*)(g_attn_h + row * kHW);   // 288 half2 per row
    __half2 v[9];
#pragma unroll
    for (int k = 0; k < 9; k++) v[k] = p[lane + 32 * k];
    float m = -3.0e38f;
#pragma unroll
    for (int k = 0; k < 9; k++) {
        float2 f = __half22float2(v[k]);
        m = fmaxf(m, fmaxf(f.x, f.y));
    }
#pragma unroll
    for (int off = 16; off > 0; off >>= 1)
        m = fmaxf(m, __shfl_xor_sync(0xffffffffu, m, off));
    float e[18];
    float s = 0.f;
#pragma unroll
    for (int k = 0; k < 9; k++) {
        float2 f = __half22float2(v[k]);
        e[2 * k] = expf(f.x - m);
        e[2 * k + 1] = expf(f.y - m);
        s += e[2 * k] + e[2 * k + 1];
    }
#pragma unroll
    for (int off = 16; off > 0; off >>= 1)
        s += __shfl_xor_sync(0xffffffffu, s, off);
    float inv = 1.0f / s;
#pragma unroll
    for (int k = 0; k < 9; k++)
        p[lane + 32 * k] = __floats2half2_rn(e[2 * k] * inv, e[2 * k + 1] * inv);
}

// ---------------------------------------------------------------------------
// 6) Propagation GEMM: dst[bz,114+c,n] = sum_m A[bz,c,m]*attn[b,t0+t,n,m]
//    grid = (5 n-tiles(128), Mtiles(128), 144 bz).
// ---------------------------------------------------------------------------
__global__ __launch_bounds__(256, 2) void prop_mma_kernel(int dstSel, float* outp,
                                                          int srcSel, int dstC, int Cin,
                                                          int t0) {
    extern __shared__ __align__(16) char smem[];
    int bz = blockIdx.z;
    int b = bz / kTp, t = bz % kTp;
    int c0 = blockIdx.y * 128, n0 = blockIdx.x * 128;
    size_t abase = ((size_t)bz * Cin + c0) * kHW;
    size_t bbase = ((size_t)b * kTm1 + t0 + t) * kHW * kHW + (size_t)n0 * kHW;
    float acc[2][8][4];
    gemm_core<96, 104>(acc_buf(srcSel) + abase, kHW, g_attn_h + bbase, kHW, kHW, acc,
                       (BufP*)smem);

    int tid = threadIdx.x;
    int wid = tid >> 5, lane = tid & 31;
    int quad = lane >> 2, tq = lane & 3;
    int wm = wid & 3, wn = wid >> 2;
#pragma unroll
    for (int mi = 0; mi < 2; mi++)
#pragma unroll
        for (int rh = 0; rh < 2; rh++) {
            int rloc = wm * 32 + mi * 16 + quad + rh * 8;
            int cg = c0 + rloc;
            if (cg < Cin) {
                size_t rbase = ((size_t)bz * dstC + kCP + cg) * kHW;
#pragma unroll
                for (int ni = 0; ni < 8; ni++) {
                    int ncol = n0 + wn * 64 + ni * 8 + tq * 2;
                    if (ncol < kHW) {
                        if (dstSel == 3) {
                            float2 v = make_float2(acc[mi][ni][rh * 2],
                                                   acc[mi][ni][rh * 2 + 1]);
                            *(float2*)(outp + rbase + ncol) = v;
                        } else {
                            uint32_t hw = h2pack(acc[mi][ni][rh * 2],
                                                 acc[mi][ni][rh * 2 + 1]);
                            *(uint32_t*)(acc_buf(dstSel) + rbase + ncol) = hw;
                        }
                    }
                }
            }
        }
}

// ---------------------------------------------------------------------------
extern "C" void kernel_launch(void* const* d_in, const int* in_sizes, int n_in,
                              void* d_out, int out_size) {
    const float* x  = (const float*)d_in[0];
    const float* Wv = (const float*)d_in[1];
    const float* bv = (const float*)d_in[2];
    float* out = (float*)d_out;

    static cudaStream_t s_side = nullptr;
    static cudaEvent_t s_fork = nullptr, s_join = nullptr;
    static bool inited = false;
    if (!inited) {
        cudaFuncSetAttribute(energy_mma_kernel,
                             cudaFuncAttributeMaxDynamicSharedMemorySize, kSmemE);
        cudaFuncSetAttribute(prop_mma_kernel,
                             cudaFuncAttributeMaxDynamicSharedMemorySize, kSmemP);
        cudaStreamCreateWithFlags(&s_side, cudaStreamNonBlocking);
        cudaEventCreateWithFlags(&s_fork, cudaEventDisableTiming);
        cudaEventCreateWithFlags(&s_join, cudaEventDisableTiming);
        inited = true;
    }

    // Fork: side stream runs the vproj/pe chain (depends only on inputs),
    // concurrent with normalize -> energy -> softmax on the main stream.
    cudaEventRecord(s_fork, 0);
    cudaStreamWaitEvent(s_side, s_fork, 0);
    vproj_fused_kernel<<<dim3(kHW / 64, kBN * kT), 256, 0, s_side>>>(x, Wv, bv, out);
    pe_fill_fused_kernel<<<(kBN * kT * 18 * kHW + 255) / 256, 256, 0, s_side>>>(out);
    cudaEventRecord(s_join, s_side);

    normalize_t_kernel<<<dim3(kBN * kT, kHW / 64), 256>>>(x);
    energy_mma_kernel<<<dim3(5, 5, kNAtt), 256, kSmemE>>>();
    softmax_kernel<<<kNAtt * kHW / 8, 256>>>();

    // Join: prop1 consumes acc0 (side) + attn (main).
    cudaStreamWaitEvent(0, s_join, 0);
    prop_mma_kernel<<<dim3(5, 1, kNB), 256, kSmemP>>>(1, out, 0, 2 * kCP, kCP, 0);
    prop_mma_kernel<<<dim3(5, 2, kNB), 256, kSmemP>>>(2, out, 1, 3 * kCP, 2 * kCP, 1);
    prop_mma_kernel<<<dim3(5, 3, kNB), 256, kSmemP>>>(3, out, 2, 4 * kCP, 3 * kCP, 2);
}

// round 17
// speedup vs baseline: 1.2075x; 1.2075x over previous
#include <cuda_runtime.h>
#include <cuda_fp16.h>
#include <math.h>
#include <cstdint>

// ---------------------------------------------------------------------------
// Problem constants (fixed by setup_inputs)
// ---------------------------------------------------------------------------
namespace {
constexpr int kBN   = 16;
constexpr int kT    = 12;
constexpr int kCH   = 128;
constexpr int kH    = 24, kW = 24;
constexpr int kHW   = 576;
constexpr int kTm1  = 11;
constexpr int kTp   = 9;
constexpr int kNB   = 144;    // kBN * kTp
constexpr int kSSTA = 32;
constexpr int kCP   = 114;
constexpr int kOutC = 456;    // 4 * kCP
constexpr int kNAtt = 176;    // kBN * kTm1
constexpr float kScale = 0.0883883476483184f;  // 128^-0.5
constexpr int kKT   = 64;     // K-elements per SMEM tile (halves)
constexpr int kLds  = 72;     // smem row stride in halves (144 B, conflict-free)
}

// ---------------------------------------------------------------------------
// Low-level helpers
// ---------------------------------------------------------------------------
__device__ __forceinline__ unsigned long long pack2(float lo, float hi) {
    unsigned long long r;
    asm("mov.b64 %0, {%1, %2};" : "=l"(r) : "f"(lo), "f"(hi));
    return r;
}
__device__ __forceinline__ unsigned long long dup2(float v) { return pack2(v, v); }
__device__ __forceinline__ void ffma2(unsigned long long& d, unsigned long long a,
                                      unsigned long long b) {
    asm("fma.rn.f32x2 %0, %1, %2, %3;" : "=l"(d) : "l"(a), "l"(b), "l"(d));
}
__device__ __forceinline__ void unpack2(unsigned long long v, float& lo, float& hi) {
    asm("mov.b64 {%0, %1}, %2;" : "=f"(lo), "=f"(hi) : "l"(v));
}

// fp16 MMA m16n8k16 (legacy HMMA path -- valid on non-'a' sm_103 target)
__device__ __forceinline__ void mma16816(float* c, const uint32_t* a, const uint32_t* b) {
    asm volatile(
        "mma.sync.aligned.m16n8k16.row.col.f32.f16.f16.f32 "
        "{%0,%1,%2,%3}, {%4,%5,%6,%7}, {%8,%9}, {%0,%1,%2,%3};"
        : "+f"(c[0]), "+f"(c[1]), "+f"(c[2]), "+f"(c[3])
        : "r"(a[0]), "r"(a[1]), "r"(a[2]), "r"(a[3]), "r"(b[0]), "r"(b[1]));
}

__device__ __forceinline__ uint32_t smem_u32p(const void* p) {
    uint32_t a;
    asm("{ .reg .u64 t; cvta.to.shared.u64 t, %1; cvt.u32.u64 %0, t; }"
        : "=r"(a) : "l"(p));
    return a;
}
__device__ __forceinline__ void ldm_x4(uint32_t* r, uint32_t saddr) {
    asm volatile("ldmatrix.sync.aligned.m8n8.x4.shared.b16 {%0,%1,%2,%3}, [%4];"
                 : "=r"(r[0]), "=r"(r[1]), "=r"(r[2]), "=r"(r[3]) : "r"(saddr));
}
__device__ __forceinline__ void cpasync16(void* sdst, const void* gsrc) {
    asm volatile("cp.async.ca.shared.global [%0], [%1], 16;"
                 :: "r"(smem_u32p(sdst)), "l"(gsrc));
}
__device__ __forceinline__ void cp_commit() {
    asm volatile("cp.async.commit_group;" ::: "memory");
}
__device__ __forceinline__ void cp_wait1() {
    asm volatile("cp.async.wait_group 1;" ::: "memory");
}
__device__ __forceinline__ void cp_wait0() {
    asm volatile("cp.async.wait_group 0;" ::: "memory");
}

// pack two fp16 from floats
__device__ __forceinline__ uint32_t h2pack(float x, float y) {
    __half hx = __float2half_rn(x), hy = __float2half_rn(y);
    return ((uint32_t)__half_as_ushort(hy) << 16) | __half_as_ushort(hx);
}

// ---------------------------------------------------------------------------
// Scratch (static device globals)
// ---------------------------------------------------------------------------
__device__ __half g_xT[((size_t)kBN * kT * kHW + 64) * kCH];
// fp16 logits written by energy; softmax converts IN PLACE to attn probs.
__device__ __half g_attn_h[((size_t)kNAtt * kHW + 64) * kHW];
__device__ __half g_acc0[((size_t)kNB * kCP + 128) * kHW];
__device__ __half g_acc1[((size_t)kNB * 2 * kCP + 128) * kHW];
__device__ __half g_acc2[((size_t)kNB * 3 * kCP + 128) * kHW];

__device__ __forceinline__ __half* acc_buf(int s) {
    return s == 0 ? g_acc0 : (s == 1 ? g_acc1 : g_acc2);
}

// ---------------------------------------------------------------------------
// SMEM tile buffer (double-buffered). 128(m) x 128(n) CTA tile, K-tile = 64.
// 2 bufs * 36864 B = 73728 B/CTA -> 2 CTAs/SM.  (K-tile 96 variant spilled
// registers under the (256,2) cap and regressed in R16 -- do not re-grow.)
// ---------------------------------------------------------------------------
struct Buf {
    __half Ah[128 * kLds];   // 18432 B
    __half Bh[128 * kLds];   // 18432 B
};
constexpr int kSmemDyn = 2 * sizeof(Buf);  // 73728 B

__device__ __forceinline__ void stage_tile(
    Buf& d, const __half* __restrict__ Agh, int lda,
    const __half* __restrict__ Bgh, int ldb, int k0, int tid) {
#pragma unroll
    for (int s = 0; s < 8; s++) {
        int i = s * 256 + tid;  // 0..2047; 8 float4-chunks per 64-half row
        int row = (i >> 3) & 127, c = i & 7;
        int coff = c * 8;
        if (i < 1024)
            cpasync16(&d.Ah[row * kLds + coff], Agh + (size_t)row * lda + k0 + coff);
        else
            cpasync16(&d.Bh[row * kLds + coff], Bgh + (size_t)row * ldb + k0 + coff);
    }
}

// Load the 8 B-fragments (two 64-col halves) for one 16-wide k-step.
__device__ __forceinline__ void load_bfrags(uint32_t bf[8][2], uint32_t Bh0, uint32_t kbb) {
#pragma unroll
    for (int half = 0; half < 2; half++) {
        uint32_t roff = (uint32_t)(half * 32 * kLds * 2) + kbb;
        uint32_t t[4];
        ldm_x4(t, Bh0 + roff);
        bf[half * 4 + 0][0] = t[0]; bf[half * 4 + 0][1] = t[1];
        bf[half * 4 + 1][0] = t[2]; bf[half * 4 + 1][1] = t[3];
        ldm_x4(t, Bh0 + roff + 16 * kLds * 2);
        bf[half * 4 + 2][0] = t[0]; bf[half * 4 + 2][1] = t[1];
        bf[half * 4 + 3][0] = t[2]; bf[half * 4 + 3][1] = t[3];
    }
}

// Core: C[128x128] accumulate over K (multiple of 64). 8 warps = 4(m) x 2(n),
// warp tile 32(m) x 64(n). ldmatrix fragments; B frags software-pipelined.
__device__ __forceinline__ void gemm_core(
    const __half* __restrict__ Agh, int lda,
    const __half* __restrict__ Bgh, int ldb,
    int K, float acc[2][8][4], Buf* bufs) {
    int tid = threadIdx.x;
    int wid = tid >> 5, lane = tid & 31;
    int wm = wid & 3, wn = wid >> 2;

    int j = lane >> 3, r = lane & 7;
    uint32_t aoff = (uint32_t)(((wm * 32 + ((j & 1) << 3) + r) * kLds + ((j >> 1) << 3)) * 2);
    uint32_t boff = (uint32_t)(((wn * 64 + ((j >> 1) << 3) + r) * kLds + ((j & 1) << 3)) * 2);

#pragma unroll
    for (int i = 0; i < 2; i++)
#pragma unroll
        for (int jj = 0; jj < 8; jj++)
#pragma unroll
            for (int q = 0; q < 4; q++) acc[i][jj][q] = 0.f;

    int nt = K / kKT;
    stage_tile(bufs[0], Agh, lda, Bgh, ldb, 0, tid);
    cp_commit();
    for (int kt = 0; kt < nt; kt++) {
        if (kt + 1 < nt) {
            stage_tile(bufs[(kt + 1) & 1], Agh, lda, Bgh, ldb, (kt + 1) * kKT, tid);
            cp_commit();
            cp_wait1();
        } else {
            cp_wait0();
        }
        __syncthreads();
        Buf& b = bufs[kt & 1];
        uint32_t Ah0 = smem_u32p(b.Ah) + aoff;
        uint32_t Bh0 = smem_u32p(b.Bh) + boff;

        uint32_t bbuf[2][8][2];
        load_bfrags(bbuf[0], Bh0, 0);
#pragma unroll
        for (int kb = 0; kb < 4; kb++) {
            int cur = kb & 1;
            uint32_t kbb = (uint32_t)kb * 32;  // 16 halves = 32 bytes per k-step
            uint32_t ah[2][4];
            ldm_x4(ah[0], Ah0 + kbb);
            ldm_x4(ah[1], Ah0 + 16 * kLds * 2 + kbb);
            if (kb < 3) load_bfrags(bbuf[cur ^ 1], Bh0, kbb + 32);
#pragma unroll
            for (int jj = 0; jj < 8; jj++)
#pragma unroll
                for (int mi = 0; mi < 2; mi++)
                    mma16816(acc[mi][jj], ah[mi], bbuf[cur][jj]);
        }
        __syncthreads();
    }
}

// ---------------------------------------------------------------------------
// 1) Normalize + transpose + fp16 convert: g_xT[bt*HW+pix][c]
// ---------------------------------------------------------------------------
__global__ __launch_bounds__(256) void normalize_t_kernel(const float* __restrict__ x) {
    __shared__ float sm[128][65];
    __shared__ float psum[4][64];
    __shared__ float invs[64];
    int bt = blockIdx.x, p0 = blockIdx.y * 64;
    int tid = threadIdx.x;
    int px = tid & 63, cq = tid >> 6;
    const float* xb = x + (size_t)bt * kCH * kHW + p0;
    float s = 0.f;
#pragma unroll
    for (int j = 0; j < 32; j++) {
        int c = cq * 32 + j;
        float v = xb[(size_t)c * kHW + px];
        sm[c][px] = v;
        s += v * v;
    }
    psum[cq][px] = s;
    __syncthreads();
    if (tid < 64) {
        float tot = psum[0][tid] + psum[1][tid] + psum[2][tid] + psum[3][tid];
        invs[tid] = 1.0f / fmaxf(sqrtf(tot), 1e-12f);
    }
    __syncthreads();
    float iv = invs[px];
    size_t rb = ((size_t)bt * kHW + p0 + px) * kCH + cq * 32;
#pragma unroll
    for (int j4 = 0; j4 < 8; j4++) {
        int c = cq * 32 + j4 * 4;
        uint32_t w0 = h2pack(sm[c][px] * iv, sm[c + 1][px] * iv);
        uint32_t w1 = h2pack(sm[c + 2][px] * iv, sm[c + 3][px] * iv);
        *(uint2*)(g_xT + rb + j4 * 4) = make_uint2(w0, w1);
    }
}

// ---------------------------------------------------------------------------
// 2) Value projection FUSED with cs-scatter (channels 32..127 only).
// ---------------------------------------------------------------------------
__global__ __launch_bounds__(256) void vproj_fused_kernel(const float* __restrict__ x,
                                                          const float* __restrict__ Wv,
                                                          const float* __restrict__ bv,
                                                          float* __restrict__ outp) {
    int bt = blockIdx.y;
    int p0 = blockIdx.x * 64;
    int b = bt / kT, tt = bt % kT;
    __shared__ __align__(16) float Ws[16][100];  // [c][o'] o'=0..95
    __shared__ __align__(16) float Xs[16][68];
    int tid = threadIdx.x;
    int ty = tid >> 4, tx = tid & 15;
    unsigned long long acc[3][4];
#pragma unroll
    for (int i = 0; i < 3; i++)
#pragma unroll
        for (int j = 0; j < 4; j++) acc[i][j] = 0ULL;

    const float* xb = x + (size_t)bt * kCH * kHW;
    for (int c0 = 0; c0 < kCH; c0 += 16) {
#pragma unroll
        for (int r = 0; r < 6; r++) {            // 96 o x 16 c
            int lin = r * 256 + tid;
            int o = lin >> 4, c = lin & 15;
            Ws[c][o] = Wv[(kSSTA + o) * kCH + c0 + c];
        }
#pragma unroll
        for (int r = 0; r < 4; r++) {
            int lin = r * 256 + tid;
            int c = lin >> 6, j = lin & 63;
            Xs[c][j] = xb[(size_t)(c0 + c) * kHW + p0 + j];
        }
        __syncthreads();
#pragma unroll
        for (int c = 0; c < 16; c++) {
            float4 xv = *(const float4*)&Xs[c][tx * 4];
            float w0 = Ws[c][ty * 6 + 0], w1 = Ws[c][ty * 6 + 1];
            float w2 = Ws[c][ty * 6 + 2], w3 = Ws[c][ty * 6 + 3];
            float w4 = Ws[c][ty * 6 + 4], w5 = Ws[c][ty * 6 + 5];
            unsigned long long wp[3] = {pack2(w0, w1), pack2(w2, w3), pack2(w4, w5)};
            unsigned long long xd[4] = {dup2(xv.x), dup2(xv.y), dup2(xv.z), dup2(xv.w)};
#pragma unroll
            for (int i = 0; i < 3; i++)
#pragma unroll
                for (int j = 0; j < 4; j++) ffma2(acc[i][j], wp[i], xd[j]);
        }
        __syncthreads();
    }

#pragma unroll
    for (int i = 0; i < 3; i++) {
        int cd0 = ty * 6 + 2 * i;
        float b0 = bv[kSSTA + cd0], b1 = bv[kSSTA + cd0 + 1];
        float vlo[4], vhi[4];
#pragma unroll
        for (int j = 0; j < 4; j++) {
            float lo, hi;
            unpack2(acc[i][j], lo, hi);
            vlo[j] = lo + b0;
            vhi[j] = hi + b1;
        }
        int pix = p0 + tx * 4;
        uint2 hlo = make_uint2(h2pack(vlo[0], vlo[1]), h2pack(vlo[2], vlo[3]));
        uint2 hhi = make_uint2(h2pack(vhi[0], vhi[1]), h2pack(vhi[2], vhi[3]));
#pragma unroll
        for (int s = 0; s < 4; s++) {
            int t = tt - s;
            if (t >= 0 && t < kTp) {
                int bz = b * kTp + t;
                if (s == 3) {
                    float* d = outp + ((size_t)bz * kOutC + cd0) * kHW + pix;
                    *(float4*)d = make_float4(vlo[0], vlo[1], vlo[2], vlo[3]);
                    *(float4*)(d + kHW) = make_float4(vhi[0], vhi[1], vhi[2], vhi[3]);
                } else {
                    int dc = (s + 1) * kCP;
                    __half* d = acc_buf(s) + ((size_t)bz * dc + cd0) * kHW + pix;
                    *(uint2*)d = hlo;
                    *(uint2*)(d + kHW) = hhi;
                }
            }
        }
    }
}

// ---------------------------------------------------------------------------
// 3) Positional-encoding FUSED scatter: cs channels 96..113 for all stages.
// ---------------------------------------------------------------------------
__global__ __launch_bounds__(256) void pe_fill_fused_kernel(float* __restrict__ outp) {
    int gid = blockIdx.x * 256 + threadIdx.x;
    const int total = kBN * kT * 18 * kHW;
    if (gid >= total) return;
    int bt  = gid / (18 * kHW);
    int rem = gid % (18 * kHW);
    int c = rem / kHW, pix = rem % kHW;
    int yy = pix / kW, xx = pix % kW;
    float yc = -1.0f + 2.0f * (float)yy / (float)(kH - 1);
    float xc = -1.0f + 2.0f * (float)xx / (float)(kW - 1);
    float val;
    if (c == 0) val = yc;
    else if (c == 1) val = xc;
    else {
        int i = (c - 2) >> 2;
        int k = (c - 2) & 3;
        float coord = (k & 1) ? xc : yc;
        float f = (float)(1 << i) * 3.14159265358979323846f * coord;
        val = (k < 2) ? sinf(f) : cosf(f);
    }
    int b = bt / kT, tt = bt % kT;
    int cd = 96 + c;
    __half hv = __float2half_rn(val);
#pragma unroll
    for (int s = 0; s < 4; s++) {
        int t = tt - s;
        if (t >= 0 && t < kTp) {
            int bz = b * kTp + t;
            if (s == 3)
                outp[((size_t)bz * kOutC + cd) * kHW + pix] = val;
            else
                acc_buf(s)[((size_t)bz * (s + 1) * kCP + cd) * kHW + pix] = hv;
        }
    }
}

// ---------------------------------------------------------------------------
// 4) Energy GEMM: logits[g,n,m] = scale * sum_c qT[n,c]*kT[m,c]; out fp16.
//    grid = (5 m-tiles(128), 5 n-tiles(128), 176 g)
// ---------------------------------------------------------------------------
__global__ __launch_bounds__(256, 2) void energy_mma_kernel() {
    extern __shared__ __align__(16) char smem[];
    int g = blockIdx.z;
    int b = g / kTm1, t = g % kTm1;
    int m0 = blockIdx.y * 128, n0 = blockIdx.x * 128;
    size_t abase = ((size_t)(b * kT + t + 1) * kHW + m0) * kCH;
    size_t bbase = ((size_t)(b * kT + t) * kHW + n0) * kCH;
    float acc[2][8][4];
    gemm_core(g_xT + abase, kCH, g_xT + bbase, kCH, kCH, acc, (Buf*)smem);

    int tid = threadIdx.x;
    int wid = tid >> 5, lane = tid & 31;
    int quad = lane >> 2, tq = lane & 3;
    int wm = wid & 3, wn = wid >> 2;
    int mvalid = kHW - m0;
    __half* C = g_attn_h + (size_t)g * kHW * kHW + (size_t)m0 * kHW;
#pragma unroll
    for (int mi = 0; mi < 2; mi++)
#pragma unroll
        for (int rh = 0; rh < 2; rh++) {
            int rrow = wm * 32 + mi * 16 + quad + rh * 8;
            if (rrow < mvalid) {
#pragma unroll
                for (int ni = 0; ni < 8; ni++) {
                    int ncol = n0 + wn * 64 + ni * 8 + tq * 2;
                    if (ncol < kHW) {
                        uint32_t hw = h2pack(acc[mi][ni][rh * 2] * kScale,
                                             acc[mi][ni][rh * 2 + 1] * kScale);
                        *(uint32_t*)(C + (size_t)rrow * kHW + ncol) = hw;
                    }
                }
            }
        }
}

// ---------------------------------------------------------------------------
// 5) Softmax: one warp per row, 8 rows per block, IN PLACE fp16.
// ---------------------------------------------------------------------------
__global__ __launch_bounds__(256) void softmax_kernel() {
    int wid = threadIdx.x >> 5, lane = threadIdx.x & 31;
    size_t row = (size_t)blockIdx.x * 8 + wid;
    __half2* p = (__half2*)(g_attn_h + row * kHW);   // 288 half2 per row
    __half2 v[9];
#pragma unroll
    for (int k = 0; k < 9; k++) v[k] = p[lane + 32 * k];
    float m = -3.0e38f;
#pragma unroll
    for (int k = 0; k < 9; k++) {
        float2 f = __half22float2(v[k]);
        m = fmaxf(m, fmaxf(f.x, f.y));
    }
#pragma unroll
    for (int off = 16; off > 0; off >>= 1)
        m = fmaxf(m, __shfl_xor_sync(0xffffffffu, m, off));
    float e[18];
    float s = 0.f;
#pragma unroll
    for (int k = 0; k < 9; k++) {
        float2 f = __half22float2(v[k]);
        e[2 * k] = expf(f.x - m);
        e[2 * k + 1] = expf(f.y - m);
        s += e[2 * k] + e[2 * k + 1];
    }
#pragma unroll
    for (int off = 16; off > 0; off >>= 1)
        s += __shfl_xor_sync(0xffffffffu, s, off);
    float inv = 1.0f / s;
#pragma unroll
    for (int k = 0; k < 9; k++)
        p[lane + 32 * k] = __floats2half2_rn(e[2 * k] * inv, e[2 * k + 1] * inv);
}

// ---------------------------------------------------------------------------
// 6) Propagation GEMM: dst[bz,114+c,n] = sum_m A[bz,c,m]*attn[b,t0+t,n,m]
//    grid = (5 n-tiles(128), Mtiles(128), 144 bz).
// ---------------------------------------------------------------------------
__global__ __launch_bounds__(256, 2) void prop_mma_kernel(int dstSel, float* outp,
                                                          int srcSel, int dstC, int Cin,
                                                          int t0) {
    extern __shared__ __align__(16) char smem[];
    int bz = blockIdx.z;
    int b = bz / kTp, t = bz % kTp;
    int c0 = blockIdx.y * 128, n0 = blockIdx.x * 128;
    size_t abase = ((size_t)bz * Cin + c0) * kHW;
    size_t bbase = ((size_t)b * kTm1 + t0 + t) * kHW * kHW + (size_t)n0 * kHW;
    float acc[2][8][4];
    gemm_core(acc_buf(srcSel) + abase, kHW, g_attn_h + bbase, kHW, kHW, acc, (Buf*)smem);

    int tid = threadIdx.x;
    int wid = tid >> 5, lane = tid & 31;
    int quad = lane >> 2, tq = lane & 3;
    int wm = wid & 3, wn = wid >> 2;
#pragma unroll
    for (int mi = 0; mi < 2; mi++)
#pragma unroll
        for (int rh = 0; rh < 2; rh++) {
            int rloc = wm * 32 + mi * 16 + quad + rh * 8;
            int cg = c0 + rloc;
            if (cg < Cin) {
                size_t rbase = ((size_t)bz * dstC + kCP + cg) * kHW;
#pragma unroll
                for (int ni = 0; ni < 8; ni++) {
                    int ncol = n0 + wn * 64 + ni * 8 + tq * 2;
                    if (ncol < kHW) {
                        if (dstSel == 3) {
                            float2 v = make_float2(acc[mi][ni][rh * 2],
                                                   acc[mi][ni][rh * 2 + 1]);
                            *(float2*)(outp + rbase + ncol) = v;
                        } else {
                            uint32_t hw = h2pack(acc[mi][ni][rh * 2],
                                                 acc[mi][ni][rh * 2 + 1]);
                            *(uint32_t*)(acc_buf(dstSel) + rbase + ncol) = hw;
                        }
                    }
                }
            }
        }
}

// ---------------------------------------------------------------------------
extern "C" void kernel_launch(void* const* d_in, const int* in_sizes, int n_in,
                              void* d_out, int out_size) {
    const float* x  = (const float*)d_in[0];
    const float* Wv = (const float*)d_in[1];
    const float* bv = (const float*)d_in[2];
    float* out = (float*)d_out;

    static cudaStream_t s_side = nullptr;
    static cudaEvent_t s_fork = nullptr, s_join = nullptr;
    static bool inited = false;
    if (!inited) {
        cudaFuncSetAttribute(energy_mma_kernel,
                             cudaFuncAttributeMaxDynamicSharedMemorySize, kSmemDyn);
        cudaFuncSetAttribute(prop_mma_kernel,
                             cudaFuncAttributeMaxDynamicSharedMemorySize, kSmemDyn);
        cudaStreamCreateWithFlags(&s_side, cudaStreamNonBlocking);
        cudaEventCreateWithFlags(&s_fork, cudaEventDisableTiming);
        cudaEventCreateWithFlags(&s_join, cudaEventDisableTiming);
        inited = true;
    }

    // Fork: side stream runs the vproj/pe chain (depends only on inputs),
    // concurrent with normalize -> energy -> softmax on the main stream.
    cudaEventRecord(s_fork, 0);
    cudaStreamWaitEvent(s_side, s_fork, 0);
    vproj_fused_kernel<<<dim3(kHW / 64, kBN * kT), 256, 0, s_side>>>(x, Wv, bv, out);
    pe_fill_fused_kernel<<<(kBN * kT * 18 * kHW + 255) / 256, 256, 0, s_side>>>(out);
    cudaEventRecord(s_join, s_side);

    normalize_t_kernel<<<dim3(kBN * kT, kHW / 64), 256>>>(x);
    energy_mma_kernel<<<dim3(5, 5, kNAtt), 256, kSmemDyn>>>();
    softmax_kernel<<<kNAtt * kHW / 8, 256>>>();

    // Join: prop1 consumes acc0 (side) + attn (main).
    cudaStreamWaitEvent(0, s_join, 0);
    prop_mma_kernel<<<dim3(5, 1, kNB), 256, kSmemDyn>>>(1, out, 0, 2 * kCP, kCP, 0);
    prop_mma_kernel<<<dim3(5, 2, kNB), 256, kSmemDyn>>>(2, out, 1, 3 * kCP, 2 * kCP, 1);
    prop_mma_kernel<<<dim3(5, 3, kNB), 256, kSmemDyn>>>(3, out, 2, 4 * kCP, 3 * kCP, 2);
}